// round 3
// baseline (speedup 1.0000x reference)
#include <cuda_runtime.h>

// LBP (radius=1, 8 points, skimage 'default') over NCHW fp32, zero boundary.
// Each thread: 4-wide x 28-tall strip, rolling 3x6 register window.
// Block (56,8) = 448 threads = one full 224x224 plane; grid = planes.
// Interior row loads have no bounds checks (compile-time eliminated).

__global__ __launch_bounds__(448) void lbp_kernel(
    const float* __restrict__ in, float* __restrict__ out)
{
    constexpr int H = 224, W = 224;

    const int plane = blockIdx.x;
    const float* ip = in + (size_t)plane * (H * W);
    float*       op = out + (size_t)plane * (H * W);

    const int tx = threadIdx.x;          // column group 0..55
    const int ty = threadIdx.y;          // strip 0..7
    const int x0 = tx * 4;
    const int y0 = ty * 28;

    const bool has_left  = (tx > 0);
    const bool has_right = (tx < 55);

    // Bilinear weights (float32 of double products, as jax produces).
    const double Fd = 0.70710678;
    const double Gd = 1.0 - Fd;
    const float WD = (float)(Fd * Fd);
    const float WE = (float)(Fd * Gd);
    const float WC = (float)(Gd * Gd);

    // Rolling 3-row window: [left, v0..v3, right] per row.
    float buf[3][6];

    const float* rp = ip + y0 * W + x0;   // points at row y0
    float*       wp = op + y0 * W + x0;

    // Prologue: row y0-1 (zero for top strip) and row y0.
    if (ty == 0) {
        buf[0][0] = buf[0][1] = buf[0][2] = buf[0][3] = buf[0][4] = buf[0][5] = 0.0f;
    } else {
        const float* q = rp - W;
        const float4 v = *reinterpret_cast<const float4*>(q);
        buf[0][0] = has_left  ? q[-1] : 0.0f;
        buf[0][1] = v.x; buf[0][2] = v.y; buf[0][3] = v.z; buf[0][4] = v.w;
        buf[0][5] = has_right ? q[4]  : 0.0f;
    }
    {
        const float4 v = *reinterpret_cast<const float4*>(rp);
        buf[1][0] = has_left  ? rp[-1] : 0.0f;
        buf[1][1] = v.x; buf[1][2] = v.y; buf[1][3] = v.z; buf[1][4] = v.w;
        buf[1][5] = has_right ? rp[4]  : 0.0f;
    }
    rp += W;   // now points at row y0+1 (first row to load in the loop)

    #pragma unroll
    for (int r = 0; r < 28; r++) {
        float* B = buf[(r + 2) % 3];

        // Load row y0+r+1. In-bounds for all r<27; at r==27 only the bottom
        // strip (ty==7) runs off the image -> zeros.
        if (r == 27 && ty == 7) {
            B[0] = B[1] = B[2] = B[3] = B[4] = B[5] = 0.0f;
        } else {
            const float4 v = *reinterpret_cast<const float4*>(rp);
            B[0] = has_left  ? rp[-1] : 0.0f;
            B[1] = v.x; B[2] = v.y; B[3] = v.z; B[4] = v.w;
            B[5] = has_right ? rp[4]  : 0.0f;
        }
        rp += W;

        const float* N = buf[r % 3];
        const float* C = buf[(r + 1) % 3];
        const float* S = B;

        float4 res;
        float* resp = &res.x;

        #pragma unroll
        for (int i = 0; i < 4; i++) {
            const float nw = N[i], nn = N[i + 1], ne = N[i + 2];
            const float ww = C[i], c  = C[i + 1], ee = C[i + 2];
            const float sw = S[i], ss = S[i + 1], se = S[i + 2];

            // Diagonal bilinear samples; expressions identical to the
            // bit-exact round-2 kernel (same FMA contraction).
            const float v1 = ((WE * nn + WD * ne) + WC * c) + WE * ee; // up-right
            const float v3 = ((WD * nw + WE * nn) + WE * ww) + WC * c; // up-left
            const float v5 = ((WE * ww + WC * c) + WD * sw) + WE * ss; // down-left
            const float v7 = ((WC * c + WE * ee) + WE * ss) + WD * se; // down-right

            float code = (ee >= c) ? 1.0f : 0.0f;   // p=0: east
            if (v1 >= c) code += 2.0f;              // p=1
            if (nn >= c) code += 4.0f;              // p=2: north
            if (v3 >= c) code += 8.0f;              // p=3
            if (ww >= c) code += 16.0f;             // p=4: west
            if (v5 >= c) code += 32.0f;             // p=5
            if (ss >= c) code += 64.0f;             // p=6: south
            if (v7 >= c) code += 128.0f;            // p=7
            resp[i] = code;
        }

        __stcs(reinterpret_cast<float4*>(wp), res);  // streaming store
        wp += W;
    }
}

extern "C" void kernel_launch(void* const* d_in, const int* in_sizes, int n_in,
                              void* d_out, int out_size)
{
    const float* x = (const float*)d_in[0];
    float* out = (float*)d_out;

    constexpr int H = 224, W = 224;
    const int planes = out_size / (H * W);   // B*C = 1024

    dim3 block(56, 8, 1);                    // 448 threads = 14 warps, full plane
    dim3 grid(planes, 1, 1);
    lbp_kernel<<<grid, block>>>(x, out);
}

// round 4
// speedup vs baseline: 1.0045x; 1.0045x over previous
#include <cuda_runtime.h>

// LBP (radius=1, 8 points, skimage 'default') over NCHW fp32, zero boundary.
// Each thread: 4-wide x 28-tall strip, rolling 3x6 register window.
// Block (56,8) = 448 threads = one full 224x224 plane; grid = planes.
// Interior row loads have no bounds checks (compile-time eliminated).

__global__ __launch_bounds__(448) void lbp_kernel(
    const float* __restrict__ in, float* __restrict__ out)
{
    constexpr int H = 224, W = 224;

    const int plane = blockIdx.x;
    const float* ip = in + (size_t)plane * (H * W);
    float*       op = out + (size_t)plane * (H * W);

    const int tx = threadIdx.x;          // column group 0..55
    const int ty = threadIdx.y;          // strip 0..7
    const int x0 = tx * 4;
    const int y0 = ty * 28;

    const bool has_left  = (tx > 0);
    const bool has_right = (tx < 55);

    // Bilinear weights (float32 of double products, as jax produces).
    const double Fd = 0.70710678;
    const double Gd = 1.0 - Fd;
    const float WD = (float)(Fd * Fd);
    const float WE = (float)(Fd * Gd);
    const float WC = (float)(Gd * Gd);

    // Rolling 3-row window: [left, v0..v3, right] per row.
    float buf[3][6];

    const float* rp = ip + y0 * W + x0;   // points at row y0
    float*       wp = op + y0 * W + x0;

    // Prologue: row y0-1 (zero for top strip) and row y0.
    if (ty == 0) {
        buf[0][0] = buf[0][1] = buf[0][2] = buf[0][3] = buf[0][4] = buf[0][5] = 0.0f;
    } else {
        const float* q = rp - W;
        const float4 v = *reinterpret_cast<const float4*>(q);
        buf[0][0] = has_left  ? q[-1] : 0.0f;
        buf[0][1] = v.x; buf[0][2] = v.y; buf[0][3] = v.z; buf[0][4] = v.w;
        buf[0][5] = has_right ? q[4]  : 0.0f;
    }
    {
        const float4 v = *reinterpret_cast<const float4*>(rp);
        buf[1][0] = has_left  ? rp[-1] : 0.0f;
        buf[1][1] = v.x; buf[1][2] = v.y; buf[1][3] = v.z; buf[1][4] = v.w;
        buf[1][5] = has_right ? rp[4]  : 0.0f;
    }
    rp += W;   // now points at row y0+1 (first row to load in the loop)

    #pragma unroll
    for (int r = 0; r < 28; r++) {
        float* B = buf[(r + 2) % 3];

        // Load row y0+r+1. In-bounds for all r<27; at r==27 only the bottom
        // strip (ty==7) runs off the image -> zeros.
        if (r == 27 && ty == 7) {
            B[0] = B[1] = B[2] = B[3] = B[4] = B[5] = 0.0f;
        } else {
            const float4 v = *reinterpret_cast<const float4*>(rp);
            B[0] = has_left  ? rp[-1] : 0.0f;
            B[1] = v.x; B[2] = v.y; B[3] = v.z; B[4] = v.w;
            B[5] = has_right ? rp[4]  : 0.0f;
        }
        rp += W;

        const float* N = buf[r % 3];
        const float* C = buf[(r + 1) % 3];
        const float* S = B;

        float4 res;
        float* resp = &res.x;

        #pragma unroll
        for (int i = 0; i < 4; i++) {
            const float nw = N[i], nn = N[i + 1], ne = N[i + 2];
            const float ww = C[i], c  = C[i + 1], ee = C[i + 2];
            const float sw = S[i], ss = S[i + 1], se = S[i + 2];

            // Diagonal bilinear samples; expressions identical to the
            // bit-exact round-2 kernel (same FMA contraction).
            const float v1 = ((WE * nn + WD * ne) + WC * c) + WE * ee; // up-right
            const float v3 = ((WD * nw + WE * nn) + WE * ww) + WC * c; // up-left
            const float v5 = ((WE * ww + WC * c) + WD * sw) + WE * ss; // down-left
            const float v7 = ((WC * c + WE * ee) + WE * ss) + WD * se; // down-right

            float code = (ee >= c) ? 1.0f : 0.0f;   // p=0: east
            if (v1 >= c) code += 2.0f;              // p=1
            if (nn >= c) code += 4.0f;              // p=2: north
            if (v3 >= c) code += 8.0f;              // p=3
            if (ww >= c) code += 16.0f;             // p=4: west
            if (v5 >= c) code += 32.0f;             // p=5
            if (ss >= c) code += 64.0f;             // p=6: south
            if (v7 >= c) code += 128.0f;            // p=7
            resp[i] = code;
        }

        __stcs(reinterpret_cast<float4*>(wp), res);  // streaming store
        wp += W;
    }
}

extern "C" void kernel_launch(void* const* d_in, const int* in_sizes, int n_in,
                              void* d_out, int out_size)
{
    const float* x = (const float*)d_in[0];
    float* out = (float*)d_out;

    constexpr int H = 224, W = 224;
    const int planes = out_size / (H * W);   // B*C = 1024

    dim3 block(56, 8, 1);                    // 448 threads = 14 warps, full plane
    dim3 grid(planes, 1, 1);
    lbp_kernel<<<grid, block>>>(x, out);
}

// round 5
// speedup vs baseline: 1.1591x; 1.1539x over previous
#include <cuda_runtime.h>

// LBP (radius=1, 8 points, skimage 'default') over NCHW fp32, zero boundary.
// Round-2 geometry (best measured): 4-wide x 8-tall strip per thread,
// block (56,4), grid (1,7,planes). New: 4-row rolling buffer with prefetch
// distance 2 — row r+2 is loaded while row r is computed, hiding L2/DRAM
// latency behind a full iteration of FP work.

__global__ __launch_bounds__(224) void lbp_kernel(
    const float* __restrict__ in, float* __restrict__ out)
{
    constexpr int H = 224, W = 224;

    const int plane = blockIdx.z;
    const float* ip = in + (size_t)plane * (H * W);
    float*       op = out + (size_t)plane * (H * W);

    const int tx = threadIdx.x;                        // column group 0..55
    const int x0 = tx * 4;
    const int y0 = blockIdx.y * 32 + threadIdx.y * 8;  // strip row base

    const bool has_left  = (tx > 0);
    const bool has_right = (tx < 55);

    // Bilinear weights (float32 of double products, as jax produces).
    const double Fd = 0.70710678;
    const double Gd = 1.0 - Fd;
    const float WD = (float)(Fd * Fd);
    const float WE = (float)(Fd * Gd);
    const float WC = (float)(Gd * Gd);

    // buf[(k+1)&3] holds relative row k (k = -1..8), [left, v0..v3, right].
    float buf[4][6];

    auto load_row = [&](float* b, int k) {
        const int gy = y0 + k;
        if ((unsigned)gy < (unsigned)H) {
            const float* rp = ip + gy * W + x0;
            const float4 v = *reinterpret_cast<const float4*>(rp);
            b[0] = has_left  ? __ldg(rp - 1) : 0.0f;
            b[1] = v.x; b[2] = v.y; b[3] = v.z; b[4] = v.w;
            b[5] = has_right ? __ldg(rp + 4) : 0.0f;
        } else {
            b[0] = b[1] = b[2] = b[3] = b[4] = b[5] = 0.0f;
        }
    };

    // Prologue: rows -1, 0, 1 into slots 0, 1, 2.
    load_row(buf[0], -1);
    load_row(buf[1], 0);
    load_row(buf[2], 1);

    float* wp = op + y0 * W + x0;

    #pragma unroll
    for (int r = 0; r < 8; r++) {
        // Prefetch row r+2 (needed first by compute r+1) into the free slot.
        if (r < 7)
            load_row(buf[(r + 3) & 3], r + 2);

        const float* N = buf[r & 3];
        const float* C = buf[(r + 1) & 3];
        const float* S = buf[(r + 2) & 3];

        float4 res;
        float* resp = &res.x;

        #pragma unroll
        for (int i = 0; i < 4; i++) {
            const float nw = N[i], nn = N[i + 1], ne = N[i + 2];
            const float ww = C[i], c  = C[i + 1], ee = C[i + 2];
            const float sw = S[i], ss = S[i + 1], se = S[i + 2];

            // Diagonal bilinear samples; expressions identical to the
            // bit-exact round-2 kernel (same FMA contraction).
            const float v1 = ((WE * nn + WD * ne) + WC * c) + WE * ee; // up-right
            const float v3 = ((WD * nw + WE * nn) + WE * ww) + WC * c; // up-left
            const float v5 = ((WE * ww + WC * c) + WD * sw) + WE * ss; // down-left
            const float v7 = ((WC * c + WE * ee) + WE * ss) + WD * se; // down-right

            float code = (ee >= c) ? 1.0f : 0.0f;   // p=0: east
            if (v1 >= c) code += 2.0f;              // p=1
            if (nn >= c) code += 4.0f;              // p=2: north
            if (v3 >= c) code += 8.0f;              // p=3
            if (ww >= c) code += 16.0f;             // p=4: west
            if (v5 >= c) code += 32.0f;             // p=5
            if (ss >= c) code += 64.0f;             // p=6: south
            if (v7 >= c) code += 128.0f;            // p=7
            resp[i] = code;
        }

        __stcs(reinterpret_cast<float4*>(wp), res);  // streaming store
        wp += W;
    }
}

extern "C" void kernel_launch(void* const* d_in, const int* in_sizes, int n_in,
                              void* d_out, int out_size)
{
    const float* x = (const float*)d_in[0];
    float* out = (float*)d_out;

    constexpr int H = 224, W = 224;
    const int planes = out_size / (H * W);   // B*C = 1024

    dim3 block(56, 4, 1);                    // 224 threads
    dim3 grid(1, 7, planes);
    lbp_kernel<<<grid, block>>>(x, out);
}

// round 6
// speedup vs baseline: 1.1641x; 1.0043x over previous
#include <cuda_runtime.h>

// LBP (radius=1, 8 points, skimage 'default') over NCHW fp32, zero boundary.
// Round-2 geometry (best measured): 4-wide x 8-tall strip per thread,
// block (56,4), grid (1,7,planes). New: 4-row rolling buffer with prefetch
// distance 2 — row r+2 is loaded while row r is computed, hiding L2/DRAM
// latency behind a full iteration of FP work.

__global__ __launch_bounds__(224) void lbp_kernel(
    const float* __restrict__ in, float* __restrict__ out)
{
    constexpr int H = 224, W = 224;

    const int plane = blockIdx.z;
    const float* ip = in + (size_t)plane * (H * W);
    float*       op = out + (size_t)plane * (H * W);

    const int tx = threadIdx.x;                        // column group 0..55
    const int x0 = tx * 4;
    const int y0 = blockIdx.y * 32 + threadIdx.y * 8;  // strip row base

    const bool has_left  = (tx > 0);
    const bool has_right = (tx < 55);

    // Bilinear weights (float32 of double products, as jax produces).
    const double Fd = 0.70710678;
    const double Gd = 1.0 - Fd;
    const float WD = (float)(Fd * Fd);
    const float WE = (float)(Fd * Gd);
    const float WC = (float)(Gd * Gd);

    // buf[(k+1)&3] holds relative row k (k = -1..8), [left, v0..v3, right].
    float buf[4][6];

    auto load_row = [&](float* b, int k) {
        const int gy = y0 + k;
        if ((unsigned)gy < (unsigned)H) {
            const float* rp = ip + gy * W + x0;
            const float4 v = *reinterpret_cast<const float4*>(rp);
            b[0] = has_left  ? __ldg(rp - 1) : 0.0f;
            b[1] = v.x; b[2] = v.y; b[3] = v.z; b[4] = v.w;
            b[5] = has_right ? __ldg(rp + 4) : 0.0f;
        } else {
            b[0] = b[1] = b[2] = b[3] = b[4] = b[5] = 0.0f;
        }
    };

    // Prologue: rows -1, 0, 1 into slots 0, 1, 2.
    load_row(buf[0], -1);
    load_row(buf[1], 0);
    load_row(buf[2], 1);

    float* wp = op + y0 * W + x0;

    #pragma unroll
    for (int r = 0; r < 8; r++) {
        // Prefetch row r+2 (needed first by compute r+1) into the free slot.
        if (r < 7)
            load_row(buf[(r + 3) & 3], r + 2);

        const float* N = buf[r & 3];
        const float* C = buf[(r + 1) & 3];
        const float* S = buf[(r + 2) & 3];

        float4 res;
        float* resp = &res.x;

        #pragma unroll
        for (int i = 0; i < 4; i++) {
            const float nw = N[i], nn = N[i + 1], ne = N[i + 2];
            const float ww = C[i], c  = C[i + 1], ee = C[i + 2];
            const float sw = S[i], ss = S[i + 1], se = S[i + 2];

            // Diagonal bilinear samples; expressions identical to the
            // bit-exact round-2 kernel (same FMA contraction).
            const float v1 = ((WE * nn + WD * ne) + WC * c) + WE * ee; // up-right
            const float v3 = ((WD * nw + WE * nn) + WE * ww) + WC * c; // up-left
            const float v5 = ((WE * ww + WC * c) + WD * sw) + WE * ss; // down-left
            const float v7 = ((WC * c + WE * ee) + WE * ss) + WD * se; // down-right

            float code = (ee >= c) ? 1.0f : 0.0f;   // p=0: east
            if (v1 >= c) code += 2.0f;              // p=1
            if (nn >= c) code += 4.0f;              // p=2: north
            if (v3 >= c) code += 8.0f;              // p=3
            if (ww >= c) code += 16.0f;             // p=4: west
            if (v5 >= c) code += 32.0f;             // p=5
            if (ss >= c) code += 64.0f;             // p=6: south
            if (v7 >= c) code += 128.0f;            // p=7
            resp[i] = code;
        }

        __stcs(reinterpret_cast<float4*>(wp), res);  // streaming store
        wp += W;
    }
}

extern "C" void kernel_launch(void* const* d_in, const int* in_sizes, int n_in,
                              void* d_out, int out_size)
{
    const float* x = (const float*)d_in[0];
    float* out = (float*)d_out;

    constexpr int H = 224, W = 224;
    const int planes = out_size / (H * W);   // B*C = 1024

    dim3 block(56, 4, 1);                    // 224 threads
    dim3 grid(1, 7, planes);
    lbp_kernel<<<grid, block>>>(x, out);
}

// round 7
// speedup vs baseline: 1.1657x; 1.0013x over previous
#include <cuda_runtime.h>

// LBP (radius=1, 8 points, skimage 'default') over NCHW fp32, zero boundary.
// Round-2 geometry (best measured): 4-wide x 8-tall strip per thread,
// block (56,4), grid (1,7,planes). New: 4-row rolling buffer with prefetch
// distance 2 — row r+2 is loaded while row r is computed, hiding L2/DRAM
// latency behind a full iteration of FP work.

__global__ __launch_bounds__(224) void lbp_kernel(
    const float* __restrict__ in, float* __restrict__ out)
{
    constexpr int H = 224, W = 224;

    const int plane = blockIdx.z;
    const float* ip = in + (size_t)plane * (H * W);
    float*       op = out + (size_t)plane * (H * W);

    const int tx = threadIdx.x;                        // column group 0..55
    const int x0 = tx * 4;
    const int y0 = blockIdx.y * 32 + threadIdx.y * 8;  // strip row base

    const bool has_left  = (tx > 0);
    const bool has_right = (tx < 55);

    // Bilinear weights (float32 of double products, as jax produces).
    const double Fd = 0.70710678;
    const double Gd = 1.0 - Fd;
    const float WD = (float)(Fd * Fd);
    const float WE = (float)(Fd * Gd);
    const float WC = (float)(Gd * Gd);

    // buf[(k+1)&3] holds relative row k (k = -1..8), [left, v0..v3, right].
    float buf[4][6];

    auto load_row = [&](float* b, int k) {
        const int gy = y0 + k;
        if ((unsigned)gy < (unsigned)H) {
            const float* rp = ip + gy * W + x0;
            const float4 v = *reinterpret_cast<const float4*>(rp);
            b[0] = has_left  ? __ldg(rp - 1) : 0.0f;
            b[1] = v.x; b[2] = v.y; b[3] = v.z; b[4] = v.w;
            b[5] = has_right ? __ldg(rp + 4) : 0.0f;
        } else {
            b[0] = b[1] = b[2] = b[3] = b[4] = b[5] = 0.0f;
        }
    };

    // Prologue: rows -1, 0, 1 into slots 0, 1, 2.
    load_row(buf[0], -1);
    load_row(buf[1], 0);
    load_row(buf[2], 1);

    float* wp = op + y0 * W + x0;

    #pragma unroll
    for (int r = 0; r < 8; r++) {
        // Prefetch row r+2 (needed first by compute r+1) into the free slot.
        if (r < 7)
            load_row(buf[(r + 3) & 3], r + 2);

        const float* N = buf[r & 3];
        const float* C = buf[(r + 1) & 3];
        const float* S = buf[(r + 2) & 3];

        float4 res;
        float* resp = &res.x;

        #pragma unroll
        for (int i = 0; i < 4; i++) {
            const float nw = N[i], nn = N[i + 1], ne = N[i + 2];
            const float ww = C[i], c  = C[i + 1], ee = C[i + 2];
            const float sw = S[i], ss = S[i + 1], se = S[i + 2];

            // Diagonal bilinear samples; expressions identical to the
            // bit-exact round-2 kernel (same FMA contraction).
            const float v1 = ((WE * nn + WD * ne) + WC * c) + WE * ee; // up-right
            const float v3 = ((WD * nw + WE * nn) + WE * ww) + WC * c; // up-left
            const float v5 = ((WE * ww + WC * c) + WD * sw) + WE * ss; // down-left
            const float v7 = ((WC * c + WE * ee) + WE * ss) + WD * se; // down-right

            float code = (ee >= c) ? 1.0f : 0.0f;   // p=0: east
            if (v1 >= c) code += 2.0f;              // p=1
            if (nn >= c) code += 4.0f;              // p=2: north
            if (v3 >= c) code += 8.0f;              // p=3
            if (ww >= c) code += 16.0f;             // p=4: west
            if (v5 >= c) code += 32.0f;             // p=5
            if (ss >= c) code += 64.0f;             // p=6: south
            if (v7 >= c) code += 128.0f;            // p=7
            resp[i] = code;
        }

        __stcs(reinterpret_cast<float4*>(wp), res);  // streaming store
        wp += W;
    }
}

extern "C" void kernel_launch(void* const* d_in, const int* in_sizes, int n_in,
                              void* d_out, int out_size)
{
    const float* x = (const float*)d_in[0];
    float* out = (float*)d_out;

    constexpr int H = 224, W = 224;
    const int planes = out_size / (H * W);   // B*C = 1024

    dim3 block(56, 4, 1);                    // 224 threads
    dim3 grid(1, 7, planes);
    lbp_kernel<<<grid, block>>>(x, out);
}